// round 3
// baseline (speedup 1.0000x reference)
#include <cuda_runtime.h>
#include <math.h>
#include <stdint.h>

#define NN 50000
#define D 256
#define NE 800000

// Scratch (allocation-free rule: __device__ globals)
__device__ float g_y[(size_t)NN * D];  // x + agg accumulator
__device__ float g_x[(size_t)NN * D];  // layer outputs

// ---------------------------------------------------------------------------
// init: y = x  (so edge atomics produce x + agg directly)
// ---------------------------------------------------------------------------
__global__ void copy_kernel(float4* __restrict__ dst, const float4* __restrict__ src, int n4) {
    int i = blockIdx.x * blockDim.x + threadIdx.x;
    if (i < n4) dst[i] = src[i];
}

// ---------------------------------------------------------------------------
// SPMM: one warp per edge. Each lane handles 8 columns (2x float4).
// red.global.add.v4.f32 (sm_90+) quarters the atomic lane-op count.
// ---------------------------------------------------------------------------
__device__ __forceinline__ void red_add_v4(float* p, float4 v) {
    asm volatile("red.global.add.v4.f32 [%0], {%1, %2, %3, %4};"
                 :: "l"(p), "f"(v.x), "f"(v.y), "f"(v.z), "f"(v.w) : "memory");
}

__global__ void spmm_kernel(const float* __restrict__ x,
                            const int* __restrict__ src,
                            const int* __restrict__ dst,
                            const float* __restrict__ ew,
                            float* __restrict__ y, int nedges) {
    int e = (blockIdx.x * blockDim.x + threadIdx.x) >> 5;
    if (e >= nedges) return;
    int lane = threadIdx.x & 31;
    int s = __ldg(src + e);
    int d = __ldg(dst + e);
    float w = __ldg(ew + e);
    const float4* xr = reinterpret_cast<const float4*>(x + (size_t)s * D);
    float* yr = y + (size_t)d * D;
    float4 a = xr[lane];
    float4 b = xr[lane + 32];
    a.x *= w; a.y *= w; a.z *= w; a.w *= w;
    b.x *= w; b.y *= w; b.z *= w; b.w *= w;
    red_add_v4(yr + lane * 4, a);
    red_add_v4(yr + 128 + lane * 4, b);
}

// ---------------------------------------------------------------------------
// Fused GEMM (+bias [+LayerNorm +GELU]) : out = f(Y @ W + b)
// Tile: BM=64 rows x 256 cols, BK=32. 256 threads = 16x16.
// Thread (tx,ty): rows ty*4..+3, cols {tx, tx+16, ..., tx+240} (strided ->
// conflict-free Bs reads and clean half-warp LN reduction).
// ---------------------------------------------------------------------------
template<bool LNGELU>
__global__ void __launch_bounds__(256)
gemm_kernel(const float* __restrict__ Y, const float* __restrict__ W,
            const float* __restrict__ bias, const float* __restrict__ gamma,
            const float* __restrict__ beta, float* __restrict__ out, int n) {
    __shared__ float As[64][36];    // +4 pad: kills half-warp bank conflict on a-frag
    __shared__ float Bs[32][256];

    int tid = threadIdx.x;
    int tx = tid & 15;
    int ty = tid >> 4;
    int m0 = blockIdx.x * 64;

    float acc[4][16];
#pragma unroll
    for (int i = 0; i < 4; i++)
#pragma unroll
        for (int j = 0; j < 16; j++) acc[i][j] = 0.f;

    for (int k0 = 0; k0 < D; k0 += 32) {
        // Load A tile: 64x32 floats, coalesced 128B per warp-row
#pragma unroll
        for (int i = 0; i < 8; i++) {
            int idx = tid + 256 * i;
            int r = idx >> 5, kk = idx & 31;
            int gr = m0 + r;
            As[r][kk] = (gr < n) ? Y[(size_t)gr * D + k0 + kk] : 0.f;
        }
        // Load B tile: 32x256 floats via float4, coalesced
#pragma unroll
        for (int i = 0; i < 8; i++) {
            int idx = tid + 256 * i;
            int r = idx >> 6, c4 = idx & 63;
            *reinterpret_cast<float4*>(&Bs[r][c4 * 4]) =
                *reinterpret_cast<const float4*>(W + (size_t)(k0 + r) * D + c4 * 4);
        }
        __syncthreads();

#pragma unroll
        for (int kk = 0; kk < 32; kk++) {
            float a[4], bf[16];
#pragma unroll
            for (int i = 0; i < 4; i++) a[i] = As[ty * 4 + i][kk];
#pragma unroll
            for (int j = 0; j < 16; j++) bf[j] = Bs[kk][j * 16 + tx];
#pragma unroll
            for (int i = 0; i < 4; i++)
#pragma unroll
                for (int j = 0; j < 16; j++) acc[i][j] = fmaf(a[i], bf[j], acc[i][j]);
        }
        __syncthreads();
    }

    // Epilogue
#pragma unroll
    for (int i = 0; i < 4; i++) {
        int gr = m0 + ty * 4 + i;
        float v[16];
        if (LNGELU) {
            float s = 0.f;
#pragma unroll
            for (int j = 0; j < 16; j++) {
                v[j] = acc[i][j] + __ldg(bias + j * 16 + tx);
                s += v[j];
            }
            // half-warp (16-lane) reduction: row is owned by lanes sharing ty
#pragma unroll
            for (int o = 1; o < 16; o <<= 1) s += __shfl_xor_sync(0xffffffffu, s, o);
            float mean = s * (1.f / 256.f);
            float s2 = 0.f;
#pragma unroll
            for (int j = 0; j < 16; j++) {
                float dvl = v[j] - mean;
                s2 += dvl * dvl;
            }
#pragma unroll
            for (int o = 1; o < 16; o <<= 1) s2 += __shfl_xor_sync(0xffffffffu, s2, o);
            float rstd = rsqrtf(s2 * (1.f / 256.f) + 1e-5f);
            if (gr < n) {
#pragma unroll
                for (int j = 0; j < 16; j++) {
                    int col = j * 16 + tx;
                    float t = (v[j] - mean) * rstd * __ldg(gamma + col) + __ldg(beta + col);
                    float ge = 0.5f * t * (1.f + erff(t * 0.70710678118654752f));
                    out[(size_t)gr * D + col] = ge;
                }
            }
        } else {
            if (gr < n) {
#pragma unroll
                for (int j = 0; j < 16; j++) {
                    int col = j * 16 + tx;
                    out[(size_t)gr * D + col] = acc[i][j] + __ldg(bias + col);
                }
            }
        }
    }
}

// ---------------------------------------------------------------------------
// launch
// ---------------------------------------------------------------------------
extern "C" void kernel_launch(void* const* d_in, const int* in_sizes, int n_in,
                              void* d_out, int out_size) {
    const float* node = (const float*)d_in[0];
    const int*   src  = (const int*)d_in[1];
    const int*   dst  = (const int*)d_in[2];
    const float* ew   = (const float*)d_in[3];
    const float* W1   = (const float*)d_in[4];
    const float* b1   = (const float*)d_in[5];
    const float* g1   = (const float*)d_in[6];
    const float* be1  = (const float*)d_in[7];
    const float* W2   = (const float*)d_in[8];
    const float* b2   = (const float*)d_in[9];
    const float* g2   = (const float*)d_in[10];
    const float* be2  = (const float*)d_in[11];
    const float* Wp   = (const float*)d_in[12];
    const float* bp   = (const float*)d_in[13];
    float* out = (float*)d_out;

    int n = in_sizes[0] / D;
    int nedges = in_sizes[1];

    float* y = nullptr;
    float* x = nullptr;
    cudaGetSymbolAddress((void**)&y, g_y);
    cudaGetSymbolAddress((void**)&x, g_x);

    int n4 = n * (D / 4);
    int copyBlocks = (n4 + 255) / 256;
    int spmmBlocks = (nedges * 32 + 255) / 256;
    int gemmBlocks = (n + 63) / 64;

    // Layer 1
    copy_kernel<<<copyBlocks, 256>>>((float4*)y, (const float4*)node, n4);
    spmm_kernel<<<spmmBlocks, 256>>>(node, src, dst, ew, y, nedges);
    gemm_kernel<true><<<gemmBlocks, 256>>>(y, W1, b1, g1, be1, x, n);

    // Layer 2
    copy_kernel<<<copyBlocks, 256>>>((float4*)y, (const float4*)x, n4);
    spmm_kernel<<<spmmBlocks, 256>>>(x, src, dst, ew, y, nedges);
    gemm_kernel<true><<<gemmBlocks, 256>>>(y, W2, b2, g2, be2, x, n);

    // Projection
    gemm_kernel<false><<<gemmBlocks, 256>>>(x, Wp, bp, nullptr, nullptr, out, n);
}